// round 8
// baseline (speedup 1.0000x reference)
#include <cuda_runtime.h>
#include <cstdint>

#define N_ROWS 16384
#define K_CODES 4096
#define D_DIM 512

#define TILE_M 128
#define TILE_N 64
#define NTILES 64                  // K_CODES / TILE_N

// int8 covers dims 0..383 (96 words), bf16 covers dims 384..511 (64 bf16x2 words)
#define A8_OFF  0                  // 128 rows x 384 B = 49152
#define ABF_OFF 49152              // 128 rows x 256 B = 32768
#define B8_OFF  81920              // 2 stages x (64 x 384 B = 24576)
#define BBF_OFF 131072             // 2 stages x (64 x 256 B = 16384)
#define CN_OFF  163840             // 4096 floats
#define DYN_BYTES (CN_OFF + K_CODES * 4)   // 180224

#define MARGIN 1.0e-3f
#define MAX_CAND 64

#define SZQ (127.0f / 6.0f)
#define SCQ (127.0f * 4096.0f)
#define MS  (-2.0f * (6.0f / 127.0f) / (127.0f * 4096.0f))

// -------- scratch --------
__device__ int      g_zq [N_ROWS * 96];    // int8 dims 0..383
__device__ unsigned g_zbf[N_ROWS * 64];    // bf16x2 dims 384..511
__device__ int      g_cq [K_CODES * 96];
__device__ unsigned g_cbf[K_CODES * 64];
__device__ float    g_znorm[N_ROWS];
__device__ float    g_cnorm[K_CODES];
__device__ int      g_idx[N_ROWS];
__device__ float    g_partial[N_ROWS];
__device__ int      g_cand[N_ROWS * MAX_CAND];
__device__ unsigned g_cnt[N_ROWS];

// -------- helpers --------
__device__ __forceinline__ unsigned smem_u32(const void* p){
    unsigned a;
    asm("{ .reg .u64 t; cvta.to.shared.u64 t, %1; cvt.u32.u64 %0, t; }" : "=r"(a) : "l"(p));
    return a;
}
__device__ __forceinline__ void cp16(unsigned s, const void* g){
    asm volatile("cp.async.cg.shared.global [%0], [%1], 16;" :: "r"(s), "l"(g) : "memory");
}
__device__ __forceinline__ void dp4(int& acc, unsigned a, unsigned b){
    asm("dp4a.s32.s32 %0, %1, %2, %0;" : "+r"(acc) : "r"(a), "r"(b));
}
__device__ __forceinline__ unsigned hfma2(unsigned a, unsigned b, unsigned c){
    unsigned d;
    asm("fma.rn.bf16x2 %0, %1, %2, %3;" : "=r"(d) : "r"(a), "r"(b), "r"(c));
    return d;
}
__device__ __forceinline__ float bf_lo(unsigned u){ return __uint_as_float(u << 16); }
__device__ __forceinline__ float bf_hi(unsigned u){ return __uint_as_float(u & 0xffff0000u); }
__device__ __forceinline__ int q8(float v, float s){
    float t = fminf(fmaxf(v * s, -127.0f), 127.0f);
    return __float2int_rn(t);
}
__device__ __forceinline__ int pack4(int a, int b, int c, int d){
    return (a & 255) | ((b & 255) << 8) | ((c & 255) << 16) | ((d & 255) << 24);
}
__device__ __forceinline__ unsigned pack_bf2(float x, float y){
    unsigned r;
    asm("cvt.rn.bf16x2.f32 %0, %1, %2;" : "=r"(r) : "f"(y), "f"(x));
    return r;
}

// -------- prep_z: exact fp64 norm + int8(0..383) + bf16(384..511) + cnt init --
__global__ void prep_z_kernel(const float* __restrict__ z){
    int w = (blockIdx.x * blockDim.x + threadIdx.x) >> 5;
    int lane = threadIdx.x & 31;
    if (w >= N_ROWS) return;
    const float4* r4 = (const float4*)(z + (size_t)w * D_DIM);
    double acc = 0.0;
    #pragma unroll
    for (int j = 0; j < 4; j++){
        int f = j * 32 + lane;            // float4 index 0..127 (4 dims each)
        float4 v = r4[f];
        acc += (double)v.x * v.x + (double)v.y * v.y
             + (double)v.z * v.z + (double)v.w * v.w;
        if (f < 96){
            g_zq[w * 96 + f] = pack4(q8(v.x,SZQ), q8(v.y,SZQ), q8(v.z,SZQ), q8(v.w,SZQ));
        } else {
            int p = (f - 96) * 2;
            g_zbf[w * 64 + p]     = pack_bf2(v.x, v.y);
            g_zbf[w * 64 + p + 1] = pack_bf2(v.z, v.w);
        }
    }
    #pragma unroll
    for (int o = 16; o > 0; o >>= 1) acc += __shfl_down_sync(0xffffffffu, acc, o);
    if (lane == 0){ g_znorm[w] = (float)acc; g_cnt[w] = 0u; }
}

// -------- prep_c: same for codebook --------
__global__ void prep_c_kernel(const float* __restrict__ cb){
    int w = (blockIdx.x * blockDim.x + threadIdx.x) >> 5;
    int lane = threadIdx.x & 31;
    if (w >= K_CODES) return;
    const float4* r4 = (const float4*)(cb + (size_t)w * D_DIM);
    double acc = 0.0;
    #pragma unroll
    for (int j = 0; j < 4; j++){
        int f = j * 32 + lane;
        float4 v = r4[f];
        acc += (double)v.x * v.x + (double)v.y * v.y
             + (double)v.z * v.z + (double)v.w * v.w;
        if (f < 96){
            g_cq[w * 96 + f] = pack4(q8(v.x,SCQ), q8(v.y,SCQ), q8(v.z,SCQ), q8(v.w,SCQ));
        } else {
            int p = (f - 96) * 2;
            g_cbf[w * 64 + p]     = pack_bf2(v.x, v.y);
            g_cbf[w * 64 + p + 1] = pack_bf2(v.z, v.w);
        }
    }
    #pragma unroll
    for (int o = 16; o > 0; o >>= 1) acc += __shfl_down_sync(0xffffffffu, acc, o);
    if (lane == 0) g_cnorm[w] = (float)acc;
}

// -------- loaders (swizzle: chunk c stored at c ^ (row & 7)) --------
__device__ __forceinline__ void load_A(unsigned smb, int rowbase, int tid){
    const char* s8 = (const char*)g_zq;
    #pragma unroll
    for (int i = 0; i < 6; i++){
        int f = tid + i * 512;
        int c = f % 24, r = f / 24;                 // r 0..127
        cp16(smb + A8_OFF + (unsigned)(r * 384 + ((c ^ (r & 7)) << 4)),
             s8 + (size_t)(rowbase + r) * 384 + c * 16);
    }
    const char* sb = (const char*)g_zbf;
    #pragma unroll
    for (int i = 0; i < 4; i++){
        int f = tid + i * 512;
        int c = f & 15, r = f >> 4;                 // r 0..127
        cp16(smb + ABF_OFF + (unsigned)(r * 256 + ((c ^ (r & 7)) << 4)),
             sb + (size_t)(rowbase + r) * 256 + c * 16);
    }
}
__device__ __forceinline__ void load_B(unsigned smb, int nt, int st, int tid){
    const char* s8 = (const char*)g_cq;
    #pragma unroll
    for (int i = 0; i < 3; i++){
        int f = tid + i * 512;
        int c = f % 24, r = f / 24;                 // r 0..63
        cp16(smb + B8_OFF + (unsigned)(st * 24576 + r * 384 + ((c ^ (r & 7)) << 4)),
             s8 + (size_t)(nt * TILE_N + r) * 384 + c * 16);
    }
    const char* sb = (const char*)g_cbf;
    #pragma unroll
    for (int i = 0; i < 2; i++){
        int f = tid + i * 512;
        int c = f & 15, r = f >> 4;                 // r 0..63
        cp16(smb + BBF_OFF + (unsigned)(st * 16384 + r * 256 + ((c ^ (r & 7)) << 4)),
             sb + (size_t)(nt * TILE_N + r) * 256 + c * 16);
    }
}

// -------- main dual-pipe kernel: dp4a + HFMA2, distances + screening --------
extern __shared__ char sm_dyn[];
__global__ __launch_bounds__(512, 1)
void vq_dual_kernel()
{
    const int tid = threadIdx.x;
    const int tx  = tid & 31;          // lane: 2 cols (tx, tx+32)
    const int ty  = tid >> 5;          // warp: 8 rows (ty*8 .. ty*8+7)
    const int rowbase = blockIdx.x * TILE_M;
    const unsigned smb = smem_u32(sm_dyn);
    float* cn_sm = (float*)(sm_dyn + CN_OFF);

    // prologue: A + B0 (group 0), B1 (group 1)
    load_A(smb, rowbase, tid);
    load_B(smb, 0, 0, tid);
    asm volatile("cp.async.commit_group;" ::: "memory");
    load_B(smb, 1, 1, tid);
    asm volatile("cp.async.commit_group;" ::: "memory");
    for (int i = tid; i < K_CODES; i += 512) cn_sm[i] = g_cnorm[i];

    int      iacc[8][2];
    unsigned bacc[8][2];
    float    run[8];
    #pragma unroll
    for (int j = 0; j < 8; j++){
        iacc[j][0] = iacc[j][1] = 0;
        bacc[j][0] = bacc[j][1] = 0u;
        run[j] = 3.4e38f;
    }

    const char* A8  = sm_dyn + A8_OFF;
    const char* ABF = sm_dyn + ABF_OFF;
    const int sxa = tx & 7;            // swizzle sel for b rows (tx and tx+32 share it)

    for (int nt = 0; nt < NTILES; nt++){
        asm volatile("cp.async.wait_group %0;" :: "n"(1) : "memory");
        if (nt == NTILES - 1)
            asm volatile("cp.async.wait_group 0;" ::: "memory");
        __syncthreads();

        const int st = nt & 1;
        const char* B8p  = sm_dyn + B8_OFF  + st * 24576;
        const char* BBFp = sm_dyn + BBF_OFF + st * 16384;

        // slices 0..15: int8 + bf16 interleaved (both pipes)
        #pragma unroll 1
        for (int c = 0; c < 16; c++){
            uint4 b0 = *(const uint4*)(B8p + tx * 384 + ((c ^ sxa) << 4));
            uint4 b1 = *(const uint4*)(B8p + (tx + 32) * 384 + ((c ^ sxa) << 4));
            uint4 f0 = *(const uint4*)(BBFp + tx * 256 + ((c ^ sxa) << 4));
            uint4 f1 = *(const uint4*)(BBFp + (tx + 32) * 256 + ((c ^ sxa) << 4));
            #pragma unroll
            for (int j = 0; j < 8; j++){
                uint4 a  = *(const uint4*)(A8  + (ty * 8 + j) * 384 + ((c ^ j) << 4));
                uint4 ab = *(const uint4*)(ABF + (ty * 8 + j) * 256 + ((c ^ j) << 4));
                dp4(iacc[j][0], a.x, b0.x); dp4(iacc[j][0], a.y, b0.y);
                dp4(iacc[j][0], a.z, b0.z); dp4(iacc[j][0], a.w, b0.w);
                dp4(iacc[j][1], a.x, b1.x); dp4(iacc[j][1], a.y, b1.y);
                dp4(iacc[j][1], a.z, b1.z); dp4(iacc[j][1], a.w, b1.w);
                bacc[j][0] = hfma2(ab.x, f0.x, bacc[j][0]);
                bacc[j][0] = hfma2(ab.y, f0.y, bacc[j][0]);
                bacc[j][0] = hfma2(ab.z, f0.z, bacc[j][0]);
                bacc[j][0] = hfma2(ab.w, f0.w, bacc[j][0]);
                bacc[j][1] = hfma2(ab.x, f1.x, bacc[j][1]);
                bacc[j][1] = hfma2(ab.y, f1.y, bacc[j][1]);
                bacc[j][1] = hfma2(ab.z, f1.z, bacc[j][1]);
                bacc[j][1] = hfma2(ab.w, f1.w, bacc[j][1]);
            }
        }
        // slices 16..23: int8 only
        #pragma unroll 1
        for (int c = 16; c < 24; c++){
            uint4 b0 = *(const uint4*)(B8p + tx * 384 + ((c ^ sxa) << 4));
            uint4 b1 = *(const uint4*)(B8p + (tx + 32) * 384 + ((c ^ sxa) << 4));
            #pragma unroll
            for (int j = 0; j < 8; j++){
                uint4 a = *(const uint4*)(A8 + (ty * 8 + j) * 384 + ((c ^ j) << 4));
                dp4(iacc[j][0], a.x, b0.x); dp4(iacc[j][0], a.y, b0.y);
                dp4(iacc[j][0], a.z, b0.z); dp4(iacc[j][0], a.w, b0.w);
                dp4(iacc[j][1], a.x, b1.x); dp4(iacc[j][1], a.y, b1.y);
                dp4(iacc[j][1], a.z, b1.z); dp4(iacc[j][1], a.w, b1.w);
            }
        }

        // ---- epilogue (warp-local; rows are warp-exclusive) ----
        const float cn0 = cn_sm[nt * TILE_N + tx];
        const float cn1 = cn_sm[nt * TILE_N + tx + 32];
        #pragma unroll
        for (int j = 0; j < 8; j++){
            float d0 = fmaf(MS, (float)iacc[j][0], cn0);
            d0 = fmaf(-2.0f, bf_lo(bacc[j][0]), d0);
            d0 = fmaf(-2.0f, bf_hi(bacc[j][0]), d0);
            float d1 = fmaf(MS, (float)iacc[j][1], cn1);
            d1 = fmaf(-2.0f, bf_lo(bacc[j][1]), d1);
            d1 = fmaf(-2.0f, bf_hi(bacc[j][1]), d1);
            float m = fminf(d0, d1);
            #pragma unroll
            for (int o = 16; o > 0; o >>= 1)
                m = fminf(m, __shfl_xor_sync(0xffffffffu, m, o));
            run[j] = fminf(run[j], m);
            float thr = run[j] + MARGIN;
            int rowg = rowbase + ty * 8 + j;
            if (d0 < thr){
                unsigned slot = atomicAdd(&g_cnt[rowg], 1u);
                if (slot < MAX_CAND) g_cand[rowg * MAX_CAND + slot] = nt * TILE_N + tx;
            }
            if (d1 < thr){
                unsigned slot = atomicAdd(&g_cnt[rowg], 1u);
                if (slot < MAX_CAND) g_cand[rowg * MAX_CAND + slot] = nt * TILE_N + tx + 32;
            }
            iacc[j][0] = iacc[j][1] = 0;
            bacc[j][0] = bacc[j][1] = 0u;
        }

        __syncthreads();   // all reads of stage st done before refill
        if (nt + 2 < NTILES){
            load_B(smb, nt + 2, st, tid);
            asm volatile("cp.async.commit_group;" ::: "memory");
        } else {
            asm volatile("cp.async.commit_group;" ::: "memory");  // keep group count
        }
    }
}

// -------- exact fp32 rescue (coalesced; warp per candidate) --------
__global__ __launch_bounds__(128, 8)
void rescue_kernel(const float* __restrict__ z, const float* __restrict__ cb)
{
    __shared__ __align__(16) float s_z[D_DIM];
    __shared__ float s_best[4];
    __shared__ int   s_bi[4];

    const int row  = blockIdx.x;
    const int tid  = threadIdx.x;
    const int warp = tid >> 5;
    const int lane = tid & 31;
    const unsigned cnt = g_cnt[row];
    const float zn = g_znorm[row];

    ((float4*)s_z)[tid] = ((const float4*)(z + (size_t)row * D_DIM))[tid];
    __syncthreads();

    const float4* z4 = (const float4*)s_z;
    float best = 3.4e38f;
    int bi = 0x7fffffff;

    if (cnt <= MAX_CAND){
        for (int k = warp; k < (int)cnt; k += 4){
            int cix = g_cand[row * MAX_CAND + k];
            const float4* c4 = (const float4*)(cb + (size_t)cix * D_DIM);
            float acc = 0.0f;
            #pragma unroll
            for (int i = 0; i < 4; i++){
                float4 cv = c4[i * 32 + lane];
                float4 zv = z4[i * 32 + lane];
                acc = fmaf(zv.x, cv.x, acc);
                acc = fmaf(zv.y, cv.y, acc);
                acc = fmaf(zv.z, cv.z, acc);
                acc = fmaf(zv.w, cv.w, acc);
            }
            #pragma unroll
            for (int o = 16; o > 0; o >>= 1)
                acc += __shfl_down_sync(0xffffffffu, acc, o);
            if (lane == 0){
                float d = fmaf(-2.0f, acc, __fadd_rn(zn, g_cnorm[cix]));
                if (d < best || (d == best && cix < bi)){ best = d; bi = cix; }
            }
        }
    } else {
        for (int cix = warp; cix < K_CODES; cix += 4){
            const float4* c4 = (const float4*)(cb + (size_t)cix * D_DIM);
            float acc = 0.0f;
            #pragma unroll
            for (int i = 0; i < 4; i++){
                float4 cv = c4[i * 32 + lane];
                float4 zv = z4[i * 32 + lane];
                acc = fmaf(zv.x, cv.x, acc);
                acc = fmaf(zv.y, cv.y, acc);
                acc = fmaf(zv.z, cv.z, acc);
                acc = fmaf(zv.w, cv.w, acc);
            }
            #pragma unroll
            for (int o = 16; o > 0; o >>= 1)
                acc += __shfl_down_sync(0xffffffffu, acc, o);
            if (lane == 0){
                float d = fmaf(-2.0f, acc, __fadd_rn(zn, g_cnorm[cix]));
                if (d < best || (d == best && cix < bi)){ best = d; bi = cix; }
            }
        }
    }

    if (lane == 0){ s_best[warp] = best; s_bi[warp] = bi; }
    __syncthreads();
    if (tid == 0){
        float bv = s_best[0]; int bix = s_bi[0];
        #pragma unroll
        for (int w = 1; w < 4; w++){
            float vv = s_best[w]; int ii = s_bi[w];
            if (vv < bv || (vv == bv && ii < bix)){ bv = vv; bix = ii; }
        }
        g_idx[row] = bix;
        g_partial[row] = bv;
    }
}

// -------- gather z_q + indices --------
__global__ void gather_kernel(const float* __restrict__ cb, float* __restrict__ out)
{
    int row = blockIdx.x, t = threadIdx.x;
    int id = g_idx[row];
    float4 v = ((const float4*)(cb + (size_t)id * D_DIM))[t];
    ((float4*)(out + (size_t)row * D_DIM))[t] = v;
    if (t == 0) out[(size_t)N_ROWS * D_DIM + row] = (float)id;
}

// -------- final loss --------
__global__ void loss_kernel(float* __restrict__ out){
    __shared__ double red[256];
    int t = threadIdx.x;
    double a = 0.0;
    for (int j = t; j < N_ROWS; j += 256) a += (double)g_partial[j];
    red[t] = a; __syncthreads();
    #pragma unroll
    for (int s = 128; s > 0; s >>= 1){
        if (t < s) red[t] += red[t + s];
        __syncthreads();
    }
    if (t == 0){
        float v = (float)(red[0] / ((double)N_ROWS * (double)D_DIM));
        out[(size_t)N_ROWS * D_DIM + N_ROWS] = __fadd_rn(v, 0.25f * v);
    }
}

extern "C" void kernel_launch(void* const* d_in, const int* in_sizes, int n_in,
                              void* d_out, int out_size)
{
    const float* z  = (const float*)d_in[0];   // [16384, 512]
    const float* cb = (const float*)d_in[1];   // [4096, 512]
    float* out = (float*)d_out;                // [z_q (N*D)] [idx (N)] [loss (1)]

    cudaFuncSetAttribute(vq_dual_kernel,
                         cudaFuncAttributeMaxDynamicSharedMemorySize, DYN_BYTES);

    prep_z_kernel<<<N_ROWS / 8, 256>>>(z);
    prep_c_kernel<<<K_CODES / 8, 256>>>(cb);
    vq_dual_kernel<<<N_ROWS / TILE_M, 512, DYN_BYTES>>>();
    rescue_kernel<<<N_ROWS, 128>>>(z, cb);
    gather_kernel<<<N_ROWS, 128>>>(cb, out);
    loss_kernel<<<1, 256>>>(out);
}

// round 9
// speedup vs baseline: 1.3039x; 1.3039x over previous
#include <cuda_runtime.h>
#include <cstdint>

#define N_ROWS 16384
#define K_CODES 4096
#define D_DIM 512

#define TILE_M 128
#define TILE_N 64
#define NTILES 64                   // K_CODES / TILE_N

#define A_BYTES 65536               // 128 rows x 512 B (resident)
#define B_OFF 65536
#define B_STAGE 32768               // 64 rows x 512 B
#define CN_OFF (B_OFF + 2 * B_STAGE)        // 131072
#define DYN_BYTES (CN_OFF + K_CODES * 4)    // 147456

#define MARGIN 1.0e-3f
#define MAX_CAND 64

#define SZQ (127.0f / 6.0f)
#define SCQ (127.0f * 4096.0f)
#define MS  (-2.0f * (6.0f / 127.0f) / (127.0f * 4096.0f))

// -------- scratch --------
__device__ int      g_zq[N_ROWS * 128];     // z int8 packed (all 512 dims)
__device__ int      g_cq[K_CODES * 128];
__device__ float    g_znorm[N_ROWS];
__device__ float    g_cnorm[K_CODES];
__device__ int      g_idx[N_ROWS];
__device__ float    g_partial[N_ROWS];
__device__ int      g_cand[N_ROWS * MAX_CAND];
__device__ unsigned g_cnt[N_ROWS];

// -------- helpers --------
__device__ __forceinline__ unsigned smem_u32(const void* p){
    unsigned a;
    asm("{ .reg .u64 t; cvta.to.shared.u64 t, %1; cvt.u32.u64 %0, t; }" : "=r"(a) : "l"(p));
    return a;
}
__device__ __forceinline__ void cp16(unsigned s, const void* g){
    asm volatile("cp.async.cg.shared.global [%0], [%1], 16;" :: "r"(s), "l"(g) : "memory");
}
__device__ __forceinline__ void dp4(int& acc, unsigned a, unsigned b){
    asm("dp4a.s32.s32 %0, %1, %2, %0;" : "+r"(acc) : "r"(a), "r"(b));
}
__device__ __forceinline__ int q8(float v, float s){
    float t = fminf(fmaxf(v * s, -127.0f), 127.0f);
    return __float2int_rn(t);
}
__device__ __forceinline__ int pack4(int a, int b, int c, int d){
    return (a & 255) | ((b & 255) << 8) | ((c & 255) << 16) | ((d & 255) << 24);
}

// -------- prep_z: fused fp64 row norm + int8 quant + cnt init --------
__global__ void prep_z_kernel(const float* __restrict__ z){
    int w = (blockIdx.x * blockDim.x + threadIdx.x) >> 5;
    int lane = threadIdx.x & 31;
    if (w >= N_ROWS) return;
    const float4* r4 = (const float4*)(z + (size_t)w * D_DIM);
    double acc = 0.0;
    #pragma unroll
    for (int j = 0; j < 4; j++){
        int widx = j * 32 + lane;
        float4 v = r4[widx];
        acc += (double)v.x * v.x + (double)v.y * v.y
             + (double)v.z * v.z + (double)v.w * v.w;
        g_zq[w * 128 + widx] = pack4(q8(v.x,SZQ), q8(v.y,SZQ), q8(v.z,SZQ), q8(v.w,SZQ));
    }
    #pragma unroll
    for (int o = 16; o > 0; o >>= 1) acc += __shfl_down_sync(0xffffffffu, acc, o);
    if (lane == 0){ g_znorm[w] = (float)acc; g_cnt[w] = 0u; }
}

// -------- prep_c: fused fp64 code norm + int8 quant --------
__global__ void prep_c_kernel(const float* __restrict__ cb){
    int w = (blockIdx.x * blockDim.x + threadIdx.x) >> 5;
    int lane = threadIdx.x & 31;
    if (w >= K_CODES) return;
    const float4* r4 = (const float4*)(cb + (size_t)w * D_DIM);
    double acc = 0.0;
    #pragma unroll
    for (int j = 0; j < 4; j++){
        int widx = j * 32 + lane;
        float4 v = r4[widx];
        acc += (double)v.x * v.x + (double)v.y * v.y
             + (double)v.z * v.z + (double)v.w * v.w;
        g_cq[w * 128 + widx] = pack4(q8(v.x,SCQ), q8(v.y,SCQ), q8(v.z,SCQ), q8(v.w,SCQ));
    }
    #pragma unroll
    for (int o = 16; o > 0; o >>= 1) acc += __shfl_down_sync(0xffffffffu, acc, o);
    if (lane == 0) g_cnorm[w] = (float)acc;
}

// -------- loaders (XOR-chunk swizzle: chunk c at c ^ ((row>>2)&7)) --------
__device__ __forceinline__ void load_A(unsigned smA, int rowbase, int tid){
    const char* src = (const char*)g_zq;
    #pragma unroll
    for (int i = 0; i < 8; i++){
        int f = tid + i * 512;
        int r = f >> 5, c = f & 31;
        unsigned dst = smA + (unsigned)(r * 512 + ((c ^ ((r >> 2) & 7)) << 4));
        cp16(dst, src + (size_t)(rowbase + r) * 512 + (c << 4));
    }
}
__device__ __forceinline__ void load_B(unsigned smb, int nt, int st, int tid){
    const char* src = (const char*)g_cq;
    #pragma unroll
    for (int i = 0; i < 4; i++){
        int f = tid + i * 512;
        int r = f >> 5, c = f & 31;
        unsigned dst = smb + (unsigned)(B_OFF + st * B_STAGE + r * 512 + ((c ^ ((r >> 2) & 7)) << 4));
        cp16(dst, src + (size_t)(nt * TILE_N + r) * 512 + (c << 4));
    }
}

// -------- main int8 dp4a kernel (512 threads, 4x4 cells/thread) --------
extern __shared__ char sm_dyn[];
__global__ __launch_bounds__(512, 1)
void vq_dp4a_kernel()
{
    const int tid = threadIdx.x;
    const int tx  = tid & 15;          // 16 x 4 cols = 64
    const int tyy = tid >> 4;          // 32 x 4 rows = 128
    const int rowbase = blockIdx.x * TILE_M;
    const unsigned smb = smem_u32(sm_dyn);
    float* cn_sm = (float*)(sm_dyn + CN_OFF);

    // prologue: A (resident) + B0 in group 0; B1 in group 1
    load_A(smb, rowbase, tid);
    load_B(smb, 0, 0, tid);
    asm volatile("cp.async.commit_group;" ::: "memory");
    load_B(smb, 1, 1, tid);
    asm volatile("cp.async.commit_group;" ::: "memory");
    for (int i = tid; i < K_CODES; i += 512) cn_sm[i] = g_cnorm[i];

    // per-thread row/col assignments
    unsigned aAddr[4]; unsigned aSw[4];
    int brow[4]; unsigned bOff[4], bSw[4];
    #pragma unroll
    for (int j = 0; j < 4; j++){
        int ar = tyy * 4 + j;
        aAddr[j] = (unsigned)(ar * 512);
        aSw[j]   = (unsigned)((ar >> 2) & 7);
        brow[j]  = tx * 4 + j;
        bOff[j]  = (unsigned)(brow[j] * 512);
        bSw[j]   = (unsigned)((brow[j] >> 2) & 7);
    }

    int acc[4][4];
    float run[4];
    #pragma unroll
    for (int r = 0; r < 4; r++){
        run[r] = 3.4e38f;
        #pragma unroll
        for (int c = 0; c < 4; c++) acc[r][c] = 0;
    }

    const char* A8 = sm_dyn;

    for (int nt = 0; nt < NTILES; nt++){
        if (nt == NTILES - 1)
            asm volatile("cp.async.wait_group 0;" ::: "memory");
        else
            asm volatile("cp.async.wait_group 1;" ::: "memory");
        __syncthreads();

        const char* Bp = sm_dyn + B_OFF + (nt & 1) * B_STAGE;

        #pragma unroll 1
        for (int kc = 0; kc < 32; kc++){
            uint4 a[4], b[4];
            #pragma unroll
            for (int j = 0; j < 4; j++){
                a[j] = *(const uint4*)(A8 + aAddr[j] + (((unsigned)kc ^ aSw[j]) << 4));
                b[j] = *(const uint4*)(Bp + bOff[j] + (((unsigned)kc ^ bSw[j]) << 4));
            }
            #pragma unroll
            for (int r = 0; r < 4; r++)
                #pragma unroll
                for (int c = 0; c < 4; c++){
                    dp4(acc[r][c], a[r].x, b[c].x);
                    dp4(acc[r][c], a[r].y, b[c].y);
                    dp4(acc[r][c], a[r].z, b[c].z);
                    dp4(acc[r][c], a[r].w, b[c].w);
                }
        }

        // ---- epilogue for tile nt (half-warp owns each row) ----
        float cnv[4];
        #pragma unroll
        for (int c = 0; c < 4; c++) cnv[c] = cn_sm[nt * TILE_N + brow[c]];
        #pragma unroll
        for (int r = 0; r < 4; r++){
            float d0 = fmaf(MS, (float)acc[r][0], cnv[0]);
            float d1 = fmaf(MS, (float)acc[r][1], cnv[1]);
            float d2 = fmaf(MS, (float)acc[r][2], cnv[2]);
            float d3 = fmaf(MS, (float)acc[r][3], cnv[3]);
            float m = fminf(fminf(d0, d1), fminf(d2, d3));
            // reduce across the 16 lanes (tx) sharing this row
            #pragma unroll
            for (int o = 8; o > 0; o >>= 1)
                m = fminf(m, __shfl_xor_sync(0xffffffffu, m, o));
            run[r] = fminf(run[r], m);
            float thr = run[r] + MARGIN;
            int rowg = rowbase + tyy * 4 + r;
            if (d0 < thr){
                unsigned s = atomicAdd(&g_cnt[rowg], 1u);
                if (s < MAX_CAND) g_cand[rowg * MAX_CAND + s] = nt * TILE_N + brow[0];
            }
            if (d1 < thr){
                unsigned s = atomicAdd(&g_cnt[rowg], 1u);
                if (s < MAX_CAND) g_cand[rowg * MAX_CAND + s] = nt * TILE_N + brow[1];
            }
            if (d2 < thr){
                unsigned s = atomicAdd(&g_cnt[rowg], 1u);
                if (s < MAX_CAND) g_cand[rowg * MAX_CAND + s] = nt * TILE_N + brow[2];
            }
            if (d3 < thr){
                unsigned s = atomicAdd(&g_cnt[rowg], 1u);
                if (s < MAX_CAND) g_cand[rowg * MAX_CAND + s] = nt * TILE_N + brow[3];
            }
            acc[r][0] = acc[r][1] = acc[r][2] = acc[r][3] = 0;
        }

        __syncthreads();    // everyone done reading stage (nt&1) before refill
        if (nt + 2 < NTILES){
            load_B(smb, nt + 2, nt & 1, tid);
            asm volatile("cp.async.commit_group;" ::: "memory");
        }
    }
}

// -------- exact fp32 rescue (coalesced; warp per candidate) --------
__global__ __launch_bounds__(128, 8)
void rescue_kernel(const float* __restrict__ z, const float* __restrict__ cb)
{
    __shared__ __align__(16) float s_z[D_DIM];
    __shared__ float s_best[4];
    __shared__ int   s_bi[4];

    const int row  = blockIdx.x;
    const int tid  = threadIdx.x;
    const int warp = tid >> 5;
    const int lane = tid & 31;
    const unsigned cnt = g_cnt[row];
    const float zn = g_znorm[row];

    ((float4*)s_z)[tid] = ((const float4*)(z + (size_t)row * D_DIM))[tid];
    __syncthreads();

    const float4* z4 = (const float4*)s_z;
    float best = 3.4e38f;
    int bi = 0x7fffffff;

    if (cnt <= MAX_CAND){
        for (int k = warp; k < (int)cnt; k += 4){
            int cix = g_cand[row * MAX_CAND + k];
            const float4* c4 = (const float4*)(cb + (size_t)cix * D_DIM);
            float acc = 0.0f;
            #pragma unroll
            for (int i = 0; i < 4; i++){
                float4 cv = c4[i * 32 + lane];
                float4 zv = z4[i * 32 + lane];
                acc = fmaf(zv.x, cv.x, acc);
                acc = fmaf(zv.y, cv.y, acc);
                acc = fmaf(zv.z, cv.z, acc);
                acc = fmaf(zv.w, cv.w, acc);
            }
            #pragma unroll
            for (int o = 16; o > 0; o >>= 1)
                acc += __shfl_down_sync(0xffffffffu, acc, o);
            if (lane == 0){
                float d = fmaf(-2.0f, acc, __fadd_rn(zn, g_cnorm[cix]));
                if (d < best || (d == best && cix < bi)){ best = d; bi = cix; }
            }
        }
    } else {
        for (int cix = warp; cix < K_CODES; cix += 4){
            const float4* c4 = (const float4*)(cb + (size_t)cix * D_DIM);
            float acc = 0.0f;
            #pragma unroll
            for (int i = 0; i < 4; i++){
                float4 cv = c4[i * 32 + lane];
                float4 zv = z4[i * 32 + lane];
                acc = fmaf(zv.x, cv.x, acc);
                acc = fmaf(zv.y, cv.y, acc);
                acc = fmaf(zv.z, cv.z, acc);
                acc = fmaf(zv.w, cv.w, acc);
            }
            #pragma unroll
            for (int o = 16; o > 0; o >>= 1)
                acc += __shfl_down_sync(0xffffffffu, acc, o);
            if (lane == 0){
                float d = fmaf(-2.0f, acc, __fadd_rn(zn, g_cnorm[cix]));
                if (d < best || (d == best && cix < bi)){ best = d; bi = cix; }
            }
        }
    }

    if (lane == 0){ s_best[warp] = best; s_bi[warp] = bi; }
    __syncthreads();
    if (tid == 0){
        float bv = s_best[0]; int bix = s_bi[0];
        #pragma unroll
        for (int w = 1; w < 4; w++){
            float vv = s_best[w]; int ii = s_bi[w];
            if (vv < bv || (vv == bv && ii < bix)){ bv = vv; bix = ii; }
        }
        g_idx[row] = bix;
        g_partial[row] = bv;
    }
}

// -------- gather z_q + indices --------
__global__ void gather_kernel(const float* __restrict__ cb, float* __restrict__ out)
{
    int row = blockIdx.x, t = threadIdx.x;
    int id = g_idx[row];
    float4 v = ((const float4*)(cb + (size_t)id * D_DIM))[t];
    ((float4*)(out + (size_t)row * D_DIM))[t] = v;
    if (t == 0) out[(size_t)N_ROWS * D_DIM + row] = (float)id;
}

// -------- final loss --------
__global__ void loss_kernel(float* __restrict__ out){
    __shared__ double red[256];
    int t = threadIdx.x;
    double a = 0.0;
    for (int j = t; j < N_ROWS; j += 256) a += (double)g_partial[j];
    red[t] = a; __syncthreads();
    #pragma unroll
    for (int s = 128; s > 0; s >>= 1){
        if (t < s) red[t] += red[t + s];
        __syncthreads();
    }
    if (t == 0){
        float v = (float)(red[0] / ((double)N_ROWS * (double)D_DIM));
        out[(size_t)N_ROWS * D_DIM + N_ROWS] = __fadd_rn(v, 0.25f * v);
    }
}

extern "C" void kernel_launch(void* const* d_in, const int* in_sizes, int n_in,
                              void* d_out, int out_size)
{
    const float* z  = (const float*)d_in[0];   // [16384, 512]
    const float* cb = (const float*)d_in[1];   // [4096, 512]
    float* out = (float*)d_out;                // [z_q (N*D)] [idx (N)] [loss (1)]

    cudaFuncSetAttribute(vq_dp4a_kernel,
                         cudaFuncAttributeMaxDynamicSharedMemorySize, DYN_BYTES);

    prep_z_kernel<<<N_ROWS / 8, 256>>>(z);
    prep_c_kernel<<<K_CODES / 8, 256>>>(cb);
    vq_dp4a_kernel<<<N_ROWS / TILE_M, 512, DYN_BYTES>>>();
    rescue_kernel<<<N_ROWS, 128>>>(z, cb);
    gather_kernel<<<N_ROWS, 128>>>(cb, out);
    loss_kernel<<<1, 256>>>(out);
}